// round 14
// baseline (speedup 1.0000x reference)
#include <cuda_runtime.h>
#include <cuda_fp16.h>
#include <cstdint>
#include <math.h>

#define B_ 8
#define L_ 2048
#define H_ 256

// ======================= PTX helpers (baseline ISA only) ===================
__device__ __forceinline__ uint32_t smem_u32(const void* p) {
    uint32_t a;
    asm("{ .reg .u64 t; cvta.to.shared.u64 t, %1; cvt.u32.u64 %0, t; }" : "=r"(a) : "l"(p));
    return a;
}
#define CP_ASYNC16(dst, src) \
    asm volatile("cp.async.cg.shared.global [%0], [%1], 16;" :: "r"(dst), "l"(src) : "memory")
#define CP_COMMIT() asm volatile("cp.async.commit_group;" ::: "memory")
#define CP_WAIT1()  asm volatile("cp.async.wait_group 1;" ::: "memory")
#define CP_WAIT0()  asm volatile("cp.async.wait_group 0;" ::: "memory")

#define LDSM_X4(r0, r1, r2, r3, a) \
    asm volatile("ldmatrix.sync.aligned.m8n8.x4.shared.b16 {%0,%1,%2,%3}, [%4];" \
        : "=r"(r0), "=r"(r1), "=r"(r2), "=r"(r3) : "r"(a))

#define MMA_F16(d, a, b) \
    asm volatile("mma.sync.aligned.m16n8k16.row.col.f32.f16.f16.f32 " \
        "{%0,%1,%2,%3}, {%4,%5,%6,%7}, {%8,%9}, {%0,%1,%2,%3};" \
        : "+f"((d)[0]), "+f"((d)[1]), "+f"((d)[2]), "+f"((d)[3]) \
        : "r"((a)[0]), "r"((a)[1]), "r"((a)[2]), "r"((a)[3]), "r"((b)[0]), "r"((b)[1]))

__device__ __forceinline__ uint32_t swz(uint32_t o) { return o ^ ((o >> 3) & 0x70); }

// ======================= scratch (device globals) ==========================
__device__ __half  d_U[(size_t)B_ * L_ * L_];        // exp(s - m_tile64), 64 MB
__device__ __half  d_gHi[B_ * L_ * H_], d_gLo[B_ * L_ * H_];
__device__ __half  d_gTs[B_ * H_ * L_];              // ID-scaled g^T, single fp16
__device__ __half  d_WhHi[B_ * L_ * H_], d_WhLo[B_ * L_ * H_];
__device__ __half  d_WPHi[H_ * H_], d_WPLo[H_ * H_];
__device__ __half  d_Wo16[H_ * 3 * H_];              // W_out single fp16
__device__ float   d_C[B_ * L_ * H_];
__device__ float   d_ID[B_ * L_];
__device__ float   d_Pmax[B_ * 32 * L_], d_Psum[B_ * 32 * L_];     // per-64-row-tile
__device__ float   d_Fac[B_ * 32 * L_];              // exp(m_tile64 - M_global)

__device__ __forceinline__ void split1h(float x, __half& h, __half& l) {
    h = __float2half_rn(x);
    l = __float2half_rn(x - __half2float(h));
}
__device__ __forceinline__ void pack_split4h(float4 v, uint2& hi, uint2& lo) {
    __half h[4], l[4];
    split1h(v.x, h[0], l[0]); split1h(v.y, h[1], l[1]);
    split1h(v.z, h[2], l[2]); split1h(v.w, h[3], l[3]);
    hi = *(uint2*)h; lo = *(uint2*)l;
}
__device__ __forceinline__ uint2 pack4h(float4 v) {
    __half h[4];
    h[0] = __float2half_rn(v.x); h[1] = __float2half_rn(v.y);
    h[2] = __float2half_rn(v.z); h[3] = __float2half_rn(v.w);
    return *(uint2*)h;
}
__device__ __forceinline__ uint32_t pack2h(float a, float b) {
    __half h0 = __float2half_rn(a), h1 = __float2half_rn(b);
    return ((uint32_t)*(uint16_t*)&h1 << 16) | *(uint16_t*)&h0;
}

// ---- smem tile loaders (K-chunk 64 halves = 128B rows, SW128) ----
__device__ __forceinline__ void tileA64(const __half* __restrict__ src, int ld,
                                        uint32_t dstBase, int tid) {
    #pragma unroll
    for (int s = 0; s < 2; s++) {
        int slot = tid + s * 256;
        int row = slot >> 3;
        int cb = (slot & 7) * 16;
        CP_ASYNC16(dstBase + swz(row * 128 + cb), (const char*)src + (size_t)row * ld * 2 + cb);
    }
}
__device__ __forceinline__ void tileB128(const __half* __restrict__ src, int ld,
                                         uint32_t dstBase, int tid) {
    #pragma unroll
    for (int s = 0; s < 4; s++) {
        int slot = tid + s * 256;
        int row = slot >> 3;
        int cb = (slot & 7) * 16;
        CP_ASYNC16(dstBase + swz(row * 128 + cb), (const char*)src + (size_t)row * ld * 2 + cb);
    }
}

// ======================= 3-pass split-fp16 NT GEMM (64x128) ================
// D = (Ah+Al)(Bh+Bl)^T via HH+HL+LH. 256 thr, 8 warps (2M x 4N, warp tile
// 32x32), K-chunk 64, 2-stage cp.async. Stage 48KB x2 = 96KB -> 2 CTAs/SM.
// AM 0: A pre-split hi/lo via cp.async | AM 2: A split in-kernel from fp32 Af
// EM 1: split-fp16 store | EM 3: u = exp(D - m_tile64col) fp16 + col stats
static constexpr int GEMM3_SMEM = 2 * 49152;

template <int AM, int EM>
__global__ __launch_bounds__(256, 2)
void gemm3p(const __half* __restrict__ Ahi, const __half* __restrict__ Alo,
            const float* __restrict__ Af, int ldaF,
            const __half* __restrict__ Bhi, const __half* __restrict__ Blo,
            __half* __restrict__ Chi, __half* __restrict__ Clo,
            float* __restrict__ Pmax, float* __restrict__ Psum,
            int K, int lda, int ldb, int ldc, long sA, long sB, long sC)
{
    extern __shared__ char smem[];
    const uint32_t sb = smem_u32(smem);
    const int tid = threadIdx.x;
    const int lane = tid & 31, wid = tid >> 5;
    const int wM = wid >> 2, wN = wid & 3;           // 2 x 4 warp grid
    const int mT = blockIdx.y * 64, nT = blockIdx.x * 128;
    const long z = blockIdx.z;

    const __half* Ah = (AM == 0) ? (Ahi + z * sA + (long)mT * lda) : nullptr;
    const __half* Al = (AM == 0) ? (Alo + z * sA + (long)mT * lda) : nullptr;
    const __half* Bh = Bhi + z * sB + (long)nT * ldb;
    const __half* Bl = Blo + z * sB + (long)nT * ldb;
    const int NC = K >> 6;

    const int c4 = tid & 15;                         // float4 col group (AM2)
    const int rA4 = tid >> 4;                        // 0..15, rows rA4 + s*16

    if (AM == 0) {
        tileA64(Ah, lda, sb,        tid);
        tileA64(Al, lda, sb + 8192, tid);
    }
    tileB128(Bh, ldb, sb + 16384, tid);
    tileB128(Bl, ldb, sb + 32768, tid);
    CP_COMMIT();

    float acc[2][4][4] = {};
    const int aRow = lane & 15;
    const int aColB = (lane >> 4) * 16;
    const int bRowP = ((lane >> 4) & 1) * 8 + (lane & 7);
    const int bColB = ((lane >> 3) & 1) * 16;

    for (int c = 0; c < NC; c++) {
        const int buf = c & 1;

        // ---- AM2: produce split-A(c) into buf ----
        if (AM == 2) {
            const int k0 = c * 64;
            #pragma unroll
            for (int s = 0; s < 4; s++) {
                float4 v = *(const float4*)(Af + (size_t)(mT + rA4 + s * 16) * ldaF + k0 + c4 * 4);
                uint2 hi, lo; pack_split4h(v, hi, lo);
                uint32_t off = swz((uint32_t)(rA4 + s * 16) * 128 + c4 * 8);
                *(uint2*)(smem + buf * 49152 + off) = hi;
                *(uint2*)(smem + buf * 49152 + 8192 + off) = lo;
            }
        }

        if (c + 1 < NC) {
            const uint32_t o1 = sb + ((c + 1) & 1) * 49152;
            const int k1 = (c + 1) * 64;
            if (AM == 0) {
                tileA64(Ah + k1, lda, o1,        tid);
                tileA64(Al + k1, lda, o1 + 8192, tid);
            }
            tileB128(Bh + k1, ldb, o1 + 16384, tid);
            tileB128(Bl + k1, ldb, o1 + 32768, tid);
            CP_COMMIT();
            CP_WAIT1();
        } else {
            CP_WAIT0();
        }
        __syncthreads();

        const uint32_t o = sb + buf * 49152;
        #pragma unroll
        for (int ks = 0; ks < 4; ks++) {
            const int kb = ks * 32;
            uint32_t rah[2][4], ral[2][4], rbh[4][2], rbl[4][2];
            #pragma unroll
            for (int mi = 0; mi < 2; mi++) {
                uint32_t off = swz((uint32_t)(wM * 32 + mi * 16 + aRow) * 128 + kb + aColB);
                LDSM_X4(rah[mi][0], rah[mi][1], rah[mi][2], rah[mi][3], o + off);
                LDSM_X4(ral[mi][0], ral[mi][1], ral[mi][2], ral[mi][3], o + 8192 + off);
            }
            #pragma unroll
            for (int p = 0; p < 2; p++) {
                uint32_t off = swz((uint32_t)(wN * 32 + p * 16 + bRowP) * 128 + kb + bColB);
                LDSM_X4(rbh[2 * p][0], rbh[2 * p][1], rbh[2 * p + 1][0], rbh[2 * p + 1][1],
                        o + 16384 + off);
                LDSM_X4(rbl[2 * p][0], rbl[2 * p][1], rbl[2 * p + 1][0], rbl[2 * p + 1][1],
                        o + 32768 + off);
            }
            #pragma unroll
            for (int mi = 0; mi < 2; mi++)
                #pragma unroll
                for (int ni = 0; ni < 4; ni++) {
                    MMA_F16(acc[mi][ni], rah[mi], rbh[ni]);
                    MMA_F16(acc[mi][ni], rah[mi], rbl[ni]);
                    MMA_F16(acc[mi][ni], ral[mi], rbh[ni]);
                }
        }
        __syncthreads();
    }

    const int rBase = mT + wM * 32 + (lane >> 2);
    const int cBase = nT + wN * 32 + (lane & 3) * 2;

    if (EM == 1) {
        #pragma unroll
        for (int mi = 0; mi < 2; mi++)
            #pragma unroll
            for (int ni = 0; ni < 4; ni++) {
                const int r0 = rBase + mi * 16;
                const int c0 = cBase + ni * 8;
                float* p = acc[mi][ni];
                #pragma unroll
                for (int hh = 0; hh < 2; hh++) {
                    __half h0, l0, h1, l1;
                    split1h(p[hh * 2 + 0], h0, l0);
                    split1h(p[hh * 2 + 1], h1, l1);
                    uint32_t ph = ((uint32_t)*(uint16_t*)&h1 << 16) | *(uint16_t*)&h0;
                    uint32_t pl = ((uint32_t)*(uint16_t*)&l1 << 16) | *(uint16_t*)&l0;
                    size_t idx = z * sC + (size_t)(r0 + hh * 8) * ldc + c0;
                    *(uint32_t*)(Chi + idx) = ph;
                    *(uint32_t*)(Clo + idx) = pl;
                }
            }
    }

    if (EM == 3) {
        float* sred = (float*)smem;          // [2][128] maxes, [2][128] sums at +256
        #pragma unroll
        for (int ni = 0; ni < 4; ni++)
            #pragma unroll
            for (int q = 0; q < 2; q++) {
                float m = -1e30f;
                #pragma unroll
                for (int mi = 0; mi < 2; mi++)
                    m = fmaxf(m, fmaxf(acc[mi][ni][q], acc[mi][ni][q + 2]));
                #pragma unroll
                for (int mk = 4; mk <= 16; mk <<= 1)
                    m = fmaxf(m, __shfl_xor_sync(0xFFFFFFFFu, m, mk));
                if (lane < 4)
                    sred[wM * 128 + wN * 32 + ni * 8 + (lane & 3) * 2 + q] = m;
            }
        __syncthreads();
        #pragma unroll
        for (int ni = 0; ni < 4; ni++) {
            const int colb = wN * 32 + ni * 8 + (lane & 3) * 2;
            const float fm0 = fmaxf(sred[colb],     sred[128 + colb]);
            const float fm1 = fmaxf(sred[colb + 1], sred[128 + colb + 1]);
            float s0 = 0.f, s1 = 0.f;
            #pragma unroll
            for (int mi = 0; mi < 2; mi++) {
                float* p = acc[mi][ni];
                float u0 = __expf(p[0] - fm0), u1 = __expf(p[1] - fm1);
                float u2 = __expf(p[2] - fm0), u3 = __expf(p[3] - fm1);
                s0 += u0 + u2; s1 += u1 + u3;
                const int r0 = rBase + mi * 16;
                const int c0 = cBase + ni * 8;
                *(uint32_t*)(Chi + z * sC + (size_t)r0 * ldc + c0) = pack2h(u0, u1);
                *(uint32_t*)(Chi + z * sC + (size_t)(r0 + 8) * ldc + c0) = pack2h(u2, u3);
            }
            #pragma unroll
            for (int mk = 4; mk <= 16; mk <<= 1) {
                s0 += __shfl_xor_sync(0xFFFFFFFFu, s0, mk);
                s1 += __shfl_xor_sync(0xFFFFFFFFu, s1, mk);
            }
            if (lane < 4) {
                sred[256 + wM * 128 + colb] = s0;
                sred[256 + wM * 128 + colb + 1] = s1;
            }
        }
        __syncthreads();
        if (tid < 128) {
            float fm = fmaxf(sred[tid], sred[128 + tid]);
            float s = sred[256 + tid] + sred[384 + tid];
            size_t idx = ((size_t)z * 32 + blockIdx.y) * L_ + nT + tid;
            Pmax[idx] = fm;
            Psum[idx] = s;
        }
    }
}

// ======================= 1-pass fp16 NT GEMM (128x128) =====================
// D = A * B^T, both single fp16; A produced in-kernel. 256 thr, 8 warps
// (2Mx4N, warp tile 64x32). Stage 32KB {A16K, B16K} x2 = 64KB.
// AM 1: A = u * Fac[tile64, j] | AM 2: A = cat(g, C, g*C)
// EM 0: fp32 store | EM 2: bias + relu fp32
static constexpr int GEMM1_SMEM = 2 * 32768;

template <int AM, int EM>
__global__ __launch_bounds__(256, 2)
void gemm1p(const __half* __restrict__ U, const float* __restrict__ Fac,
            const float* __restrict__ Af1, const float* __restrict__ Af2,
            const __half* __restrict__ Bg,
            float* __restrict__ Cf, const float* __restrict__ bias,
            int K, int ldaF, int ldb, int ldc, long sA, long sB, long sC)
{
    extern __shared__ char smem[];
    const uint32_t sb = smem_u32(smem);
    const int tid = threadIdx.x;
    const int lane = tid & 31, wid = tid >> 5;
    const int wM = wid >> 2, wN = wid & 3;           // 2 x 4 warp grid
    const int mT = blockIdx.y * 128, nT = blockIdx.x * 128;
    const long z = blockIdx.z;

    const __half* Bp = Bg + z * sB + (long)nT * ldb;
    const int NC = K >> 6;

    const int c4 = tid & 15;
    const int rA = tid >> 4;                         // 0..15, rows rA + s*16
    uint2 ua[8];
    const __half* Ug = (AM == 1) ? (U + z * sA + (size_t)mT * ldaF) : nullptr;
    const float* Facp = (AM == 1) ? (Fac + ((size_t)z * 32 + blockIdx.y * 2) * L_) : nullptr;

    if (AM == 1) {
        #pragma unroll
        for (int s = 0; s < 8; s++)
            ua[s] = *(const uint2*)(Ug + (size_t)(rA + s * 16) * ldaF + c4 * 4);
    }
    tileB128(Bp, ldb, sb + 16384, tid);
    CP_COMMIT();

    float acc[4][4][4] = {};
    const int aRow = lane & 15;
    const int aColB = (lane >> 4) * 16;
    const int bRowP = ((lane >> 4) & 1) * 8 + (lane & 7);
    const int bColB = ((lane >> 3) & 1) * 16;

    for (int c = 0; c < NC; c++) {
        const int buf = c & 1;

        // ---- produce A(c) into buf ----
        if (AM == 1) {
            const int k0 = c * 64;
            float4 fv0 = *(const float4*)(Facp + k0 + c4 * 4);
            float4 fv1 = *(const float4*)(Facp + L_ + k0 + c4 * 4);
            #pragma unroll
            for (int s = 0; s < 8; s++) {
                const float4 fv = (s < 4) ? fv0 : fv1;
                const __half* uh = (const __half*)&ua[s];
                float4 v = make_float4(__half2float(uh[0]) * fv.x,
                                       __half2float(uh[1]) * fv.y,
                                       __half2float(uh[2]) * fv.z,
                                       __half2float(uh[3]) * fv.w);
                uint32_t off = swz((uint32_t)(rA + s * 16) * 128 + c4 * 8);
                *(uint2*)(smem + buf * 32768 + off) = pack4h(v);
            }
        } else {
            const int k0 = c * 64;
            const int seg = k0 >> 8;
            const int hc = (k0 & 255) + c4 * 4;
            #pragma unroll
            for (int s = 0; s < 8; s++) {
                const size_t mrow = (size_t)(mT + rA + s * 16);
                float4 v;
                if (seg == 0) v = *(const float4*)(Af1 + mrow * ldaF + hc);
                else if (seg == 1) v = *(const float4*)(Af2 + mrow * ldaF + hc);
                else {
                    float4 g4 = *(const float4*)(Af1 + mrow * ldaF + hc);
                    float4 cc = *(const float4*)(Af2 + mrow * ldaF + hc);
                    v = make_float4(g4.x * cc.x, g4.y * cc.y, g4.z * cc.z, g4.w * cc.w);
                }
                uint32_t off = swz((uint32_t)(rA + s * 16) * 128 + c4 * 8);
                *(uint2*)(smem + buf * 32768 + off) = pack4h(v);
            }
        }

        // ---- stage chunk c+1 ----
        if (c + 1 < NC) {
            const uint32_t o1 = sb + ((c + 1) & 1) * 32768;
            const int k1 = (c + 1) * 64;
            if (AM == 1) {
                #pragma unroll
                for (int s = 0; s < 8; s++)
                    ua[s] = *(const uint2*)(Ug + (size_t)(rA + s * 16) * ldaF + k1 + c4 * 4);
            }
            tileB128(Bp + k1, ldb, o1 + 16384, tid);
            CP_COMMIT();
            CP_WAIT1();
        } else {
            CP_WAIT0();
        }
        __syncthreads();

        const uint32_t o = sb + buf * 32768;
        #pragma unroll
        for (int ks = 0; ks < 4; ks++) {
            const int kb = ks * 32;
            uint32_t rah[4][4], rbh[4][2];
            #pragma unroll
            for (int mi = 0; mi < 4; mi++) {
                uint32_t off = swz((uint32_t)(wM * 64 + mi * 16 + aRow) * 128 + kb + aColB);
                LDSM_X4(rah[mi][0], rah[mi][1], rah[mi][2], rah[mi][3], o + off);
            }
            #pragma unroll
            for (int p = 0; p < 2; p++) {
                uint32_t off = swz((uint32_t)(wN * 32 + p * 16 + bRowP) * 128 + kb + bColB);
                LDSM_X4(rbh[2 * p][0], rbh[2 * p][1], rbh[2 * p + 1][0], rbh[2 * p + 1][1],
                        o + 16384 + off);
            }
            #pragma unroll
            for (int mi = 0; mi < 4; mi++)
                #pragma unroll
                for (int ni = 0; ni < 4; ni++)
                    MMA_F16(acc[mi][ni], rah[mi], rbh[ni]);
        }
        __syncthreads();
    }

    const int rBase = mT + wM * 64 + (lane >> 2);
    const int cBase = nT + wN * 32 + (lane & 3) * 2;
    #pragma unroll
    for (int mi = 0; mi < 4; mi++)
        #pragma unroll
        for (int ni = 0; ni < 4; ni++) {
            const int r0 = rBase + mi * 16;
            const int c0 = cBase + ni * 8;
            float* p = acc[mi][ni];
            if (EM == 0) {
                float* dst = Cf + z * sC;
                *(float2*)(dst + (size_t)r0 * ldc + c0) = make_float2(p[0], p[1]);
                *(float2*)(dst + (size_t)(r0 + 8) * ldc + c0) = make_float2(p[2], p[3]);
            } else {
                float2 bv = *(const float2*)(bias + c0);
                float* dst = Cf + z * sC;
                *(float2*)(dst + (size_t)r0 * ldc + c0) =
                    make_float2(fmaxf(p[0] + bv.x, 0.f), fmaxf(p[1] + bv.y, 0.f));
                *(float2*)(dst + (size_t)(r0 + 8) * ldc + c0) =
                    make_float2(fmaxf(p[2] + bv.x, 0.f), fmaxf(p[3] + bv.y, 0.f));
            }
        }
}

// ======================= prep / softmax kernels ============================
__global__ void split_k(const float* __restrict__ x, __half* __restrict__ hi,
                        __half* __restrict__ lo, int n4)
{
    for (int i = blockIdx.x * blockDim.x + threadIdx.x; i < n4; i += gridDim.x * blockDim.x) {
        float4 v = ((const float4*)x)[i];
        uint2 h, l; pack_split4h(v, h, l);
        ((uint2*)hi)[i] = h;
        ((uint2*)lo)[i] = l;
    }
}

__global__ void convert_k(const float* __restrict__ x, __half* __restrict__ y, int n4)
{
    for (int i = blockIdx.x * blockDim.x + threadIdx.x; i < n4; i += gridDim.x * blockDim.x) {
        float4 v = ((const float4*)x)[i];
        ((uint2*)y)[i] = pack4h(v);
    }
}

// gTs[b, h, j] = ID[b,j] * g[b, j, h], single fp16
__global__ void transpose_scale(const float* __restrict__ G, const float* __restrict__ ID,
                                __half* __restrict__ T)
{
    __shared__ float t[32][33];
    const int j0 = blockIdx.x * 32, h0 = blockIdx.y * 32, b = blockIdx.z;
    const float* Gb = G + (size_t)b * L_ * H_;
    #pragma unroll
    for (int r = 0; r < 4; r++) {
        int row = threadIdx.y + r * 8;
        t[row][threadIdx.x] = Gb[(size_t)(j0 + row) * H_ + h0 + threadIdx.x]
                              * ID[b * L_ + j0 + row];
    }
    __syncthreads();
    __half* Tb = T + (size_t)b * H_ * L_;
    #pragma unroll
    for (int r = 0; r < 4; r++) {
        int hr = threadIdx.y + r * 8;
        Tb[(size_t)(h0 + hr) * L_ + j0 + threadIdx.x] = __float2half_rn(t[threadIdx.x][hr]);
    }
}

// combine 32 per-tile partials per column -> ID = 1/D, Fac[t] = exp(pm[t]-M)
__global__ void reduce_stats(const float* __restrict__ Pmax, const float* __restrict__ Psum,
                             float* __restrict__ IDo, float* __restrict__ Fac)
{
    const int idx = blockIdx.x * blockDim.x + threadIdx.x;
    const size_t base = ((size_t)(idx >> 11) * 32) * L_ + (idx & (L_ - 1));
    float M = -1e30f;
    float pm[32];
    #pragma unroll
    for (int t = 0; t < 32; t++) {
        pm[t] = Pmax[base + (size_t)t * L_];
        M = fmaxf(M, pm[t]);
    }
    float D = 0.f;
    #pragma unroll
    for (int t = 0; t < 32; t++) {
        float e = __expf(pm[t] - M);
        D += Psum[base + (size_t)t * L_] * e;
        Fac[base + (size_t)t * L_] = e;
    }
    IDo[idx] = 1.0f / D;
}

// ===========================================================================
extern "C" void kernel_launch(void* const* d_in, const int* in_sizes, int n_in,
                              void* d_out, int out_size)
{
    const float* g     = (const float*)d_in[0];
    const float* WP    = (const float*)d_in[1];
    const float* W_out = (const float*)d_in[2];
    const float* b_out = (const float*)d_in[3];
    float* out = (float*)d_out;

    float *C, *ID, *Pm, *Ps, *Fc;
    __half *U, *gHi, *gLo, *gTs, *WhHi, *WhLo, *WPHi, *WPLo, *Wo16;
    cudaGetSymbolAddress((void**)&U, d_U);
    cudaGetSymbolAddress((void**)&C, d_C);
    cudaGetSymbolAddress((void**)&ID, d_ID);
    cudaGetSymbolAddress((void**)&Pm, d_Pmax);
    cudaGetSymbolAddress((void**)&Ps, d_Psum);
    cudaGetSymbolAddress((void**)&Fc, d_Fac);
    cudaGetSymbolAddress((void**)&gHi, d_gHi);   cudaGetSymbolAddress((void**)&gLo, d_gLo);
    cudaGetSymbolAddress((void**)&gTs, d_gTs);
    cudaGetSymbolAddress((void**)&WhHi, d_WhHi); cudaGetSymbolAddress((void**)&WhLo, d_WhLo);
    cudaGetSymbolAddress((void**)&WPHi, d_WPHi); cudaGetSymbolAddress((void**)&WPLo, d_WPLo);
    cudaGetSymbolAddress((void**)&Wo16, d_Wo16);

    cudaFuncSetAttribute(gemm3p<2,1>, cudaFuncAttributeMaxDynamicSharedMemorySize, GEMM3_SMEM);
    cudaFuncSetAttribute(gemm3p<0,3>, cudaFuncAttributeMaxDynamicSharedMemorySize, GEMM3_SMEM);
    cudaFuncSetAttribute(gemm1p<1,0>, cudaFuncAttributeMaxDynamicSharedMemorySize, GEMM1_SMEM);
    cudaFuncSetAttribute(gemm1p<2,2>, cudaFuncAttributeMaxDynamicSharedMemorySize, GEMM1_SMEM);

    // streams/events for fork-join overlap (created once, before any capture)
    static cudaStream_t s2 = nullptr;
    static cudaEvent_t e0 = nullptr, e1 = nullptr;
    if (s2 == nullptr) {
        cudaStreamCreate(&s2);
        cudaEventCreateWithFlags(&e0, cudaEventDisableTiming);
        cudaEventCreateWithFlags(&e1, cudaEventDisableTiming);
    }

    // ---- fork: side stream does split(g) + convert(W_out) ----
    cudaEventRecord(e0, 0);
    cudaStreamWaitEvent(s2, e0, 0);
    split_k<<<2048, 256, 0, s2>>>(g, gHi, gLo, B_ * L_ * H_ / 4);
    convert_k<<<96, 256, 0, s2>>>(W_out, Wo16, H_ * 3 * H_ / 4);
    cudaEventRecord(e1, s2);

    // ---- main stream: WP split + Wh GEMM (reads fp32 g directly) ----
    split_k<<<64, 256>>>(WP, WPHi, WPLo, H_ * H_ / 4);

    // 1) Wh = g @ WP^T  (3-pass, A split in-kernel from fp32 g)
    gemm3p<2,1><<<dim3(2, 256, 1), 256, GEMM3_SMEM>>>(
        nullptr, nullptr, g, H_, WPHi, WPLo, WhHi, WhLo, nullptr, nullptr,
        H_, H_, H_, H_, 0, 0, 0);

    // join: S-GEMM needs gHi/gLo (and out-GEMM later needs Wo16)
    cudaStreamWaitEvent(0, e1, 0);

    // 2) u[b] = exp(Wh[b] @ g[b]^T - m_tile64) fp16 + per-tile column stats
    gemm3p<0,3><<<dim3(16, 32, B_), 256, GEMM3_SMEM>>>(
        WhHi, WhLo, nullptr, 0, gHi, gLo, U, nullptr, Pm, Ps,
        H_, H_, H_, L_, (long)L_ * H_, (long)L_ * H_, (long)L_ * L_);

    // 3) combine partials -> ID, Fac
    reduce_stats<<<(B_ * L_) / 256, 256>>>(Pm, Ps, ID, Fc);

    // 4) gTs = (ID_j * g)^T single fp16
    transpose_scale<<<dim3(L_ / 32, H_ / 32, B_), dim3(32, 8)>>>(g, ID, gTs);

    // 5) c[b] = (u * Fac) @ gTs^T  (1-pass, A in-kernel)
    gemm1p<1,0><<<dim3(2, 16, B_), 256, GEMM1_SMEM>>>(
        U, Fc, nullptr, nullptr, gTs, C, nullptr,
        L_, L_, L_, H_, (long)L_ * L_, (long)H_ * L_, (long)L_ * H_);

    // 6) out = relu(cat(g, c, g*c) @ Wo16^T + b)  (1-pass, A built in-kernel)
    gemm1p<2,2><<<dim3(2, 128, 1), 256, GEMM1_SMEM>>>(
        nullptr, nullptr, g, C, Wo16, out, b_out,
        3 * H_, H_, 3 * H_, H_, 0, 0, 0);
}

// round 15
// speedup vs baseline: 1.0014x; 1.0014x over previous
#include <cuda_runtime.h>
#include <cuda_fp16.h>
#include <cstdint>
#include <math.h>

#define B_ 8
#define L_ 2048
#define H_ 256

// ======================= PTX helpers (baseline ISA only) ===================
__device__ __forceinline__ uint32_t smem_u32(const void* p) {
    uint32_t a;
    asm("{ .reg .u64 t; cvta.to.shared.u64 t, %1; cvt.u32.u64 %0, t; }" : "=r"(a) : "l"(p));
    return a;
}
#define CP_ASYNC16(dst, src) \
    asm volatile("cp.async.cg.shared.global [%0], [%1], 16;" :: "r"(dst), "l"(src) : "memory")
#define CP_COMMIT() asm volatile("cp.async.commit_group;" ::: "memory")
#define CP_WAIT1()  asm volatile("cp.async.wait_group 1;" ::: "memory")
#define CP_WAIT0()  asm volatile("cp.async.wait_group 0;" ::: "memory")

#define LDSM_X4(r0, r1, r2, r3, a) \
    asm volatile("ldmatrix.sync.aligned.m8n8.x4.shared.b16 {%0,%1,%2,%3}, [%4];" \
        : "=r"(r0), "=r"(r1), "=r"(r2), "=r"(r3) : "r"(a))

#define MMA_F16(d, a, b) \
    asm volatile("mma.sync.aligned.m16n8k16.row.col.f32.f16.f16.f32 " \
        "{%0,%1,%2,%3}, {%4,%5,%6,%7}, {%8,%9}, {%0,%1,%2,%3};" \
        : "+f"((d)[0]), "+f"((d)[1]), "+f"((d)[2]), "+f"((d)[3]) \
        : "r"((a)[0]), "r"((a)[1]), "r"((a)[2]), "r"((a)[3]), "r"((b)[0]), "r"((b)[1]))

// f16-accumulator variant: D/C are 2 regs of packed halves
#define MMA_F16ACC(d, a, b) \
    asm volatile("mma.sync.aligned.m16n8k16.row.col.f16.f16.f16.f16 " \
        "{%0,%1}, {%2,%3,%4,%5}, {%6,%7}, {%0,%1};" \
        : "+r"((d)[0]), "+r"((d)[1]) \
        : "r"((a)[0]), "r"((a)[1]), "r"((a)[2]), "r"((a)[3]), "r"((b)[0]), "r"((b)[1]))

__device__ __forceinline__ uint32_t swz(uint32_t o) { return o ^ ((o >> 3) & 0x70); }

// ======================= scratch (device globals) ==========================
__device__ __half  d_U[(size_t)B_ * L_ * L_];        // exp(s - m_tile64), 64 MB
__device__ __half  d_gHi[B_ * L_ * H_], d_gLo[B_ * L_ * H_];
__device__ __half  d_gTs[B_ * H_ * L_];              // ID-scaled g^T, single fp16
__device__ __half  d_WhHi[B_ * L_ * H_], d_WhLo[B_ * L_ * H_];
__device__ __half  d_WPHi[H_ * H_], d_WPLo[H_ * H_];
__device__ __half  d_Wo16[H_ * 3 * H_];              // W_out single fp16
__device__ float   d_C[B_ * L_ * H_];
__device__ float   d_ID[B_ * L_];
__device__ float   d_Pmax[B_ * 32 * L_], d_Psum[B_ * 32 * L_];     // per-64-row-tile
__device__ float   d_Fac[B_ * 32 * L_];              // exp(m_tile64 - M_global)

__device__ __forceinline__ void split1h(float x, __half& h, __half& l) {
    h = __float2half_rn(x);
    l = __float2half_rn(x - __half2float(h));
}
__device__ __forceinline__ void pack_split4h(float4 v, uint2& hi, uint2& lo) {
    __half h[4], l[4];
    split1h(v.x, h[0], l[0]); split1h(v.y, h[1], l[1]);
    split1h(v.z, h[2], l[2]); split1h(v.w, h[3], l[3]);
    hi = *(uint2*)h; lo = *(uint2*)l;
}
__device__ __forceinline__ uint2 pack4h(float4 v) {
    __half h[4];
    h[0] = __float2half_rn(v.x); h[1] = __float2half_rn(v.y);
    h[2] = __float2half_rn(v.z); h[3] = __float2half_rn(v.w);
    return *(uint2*)h;
}
__device__ __forceinline__ uint32_t pack2h(float a, float b) {
    __half h0 = __float2half_rn(a), h1 = __float2half_rn(b);
    return ((uint32_t)*(uint16_t*)&h1 << 16) | *(uint16_t*)&h0;
}

// ---- smem tile loaders (K-chunk 64 halves = 128B rows, SW128) ----
__device__ __forceinline__ void tileA64(const __half* __restrict__ src, int ld,
                                        uint32_t dstBase, int tid) {
    #pragma unroll
    for (int s = 0; s < 2; s++) {
        int slot = tid + s * 256;
        int row = slot >> 3;
        int cb = (slot & 7) * 16;
        CP_ASYNC16(dstBase + swz(row * 128 + cb), (const char*)src + (size_t)row * ld * 2 + cb);
    }
}
__device__ __forceinline__ void tileB128(const __half* __restrict__ src, int ld,
                                         uint32_t dstBase, int tid) {
    #pragma unroll
    for (int s = 0; s < 4; s++) {
        int slot = tid + s * 256;
        int row = slot >> 3;
        int cb = (slot & 7) * 16;
        CP_ASYNC16(dstBase + swz(row * 128 + cb), (const char*)src + (size_t)row * ld * 2 + cb);
    }
}

// ======================= 3-pass split-fp16 NT GEMM (64x128) ================
// D = (Ah+Al)(Bh+Bl)^T. HH pass -> f32 acc; HL+LH correction passes -> f16
// acc (independent register chain, tiny magnitudes), merged in epilogue.
// 256 thr, 8 warps (2M x 4N, warp tile 32x32), K-chunk 64, 2-stage cp.async.
// Stage 48KB x2 = 96KB -> 2 CTAs/SM.
// EM 1: split-fp16 store | EM 3: u = exp(D - m_tile64col) fp16 + col stats
static constexpr int GEMM3_SMEM = 2 * 49152;

template <int EM>
__global__ __launch_bounds__(256, 2)
void gemm3p(const __half* __restrict__ Ahi, const __half* __restrict__ Alo,
            const __half* __restrict__ Bhi, const __half* __restrict__ Blo,
            __half* __restrict__ Chi, __half* __restrict__ Clo,
            float* __restrict__ Pmax, float* __restrict__ Psum,
            int K, int lda, int ldb, int ldc, long sA, long sB, long sC)
{
    extern __shared__ char smem[];
    const uint32_t sb = smem_u32(smem);
    const int tid = threadIdx.x;
    const int lane = tid & 31, wid = tid >> 5;
    const int wM = wid >> 2, wN = wid & 3;           // 2 x 4 warp grid
    const int mT = blockIdx.y * 64, nT = blockIdx.x * 128;
    const long z = blockIdx.z;

    const __half* Ah = Ahi + z * sA + (long)mT * lda;
    const __half* Al = Alo + z * sA + (long)mT * lda;
    const __half* Bh = Bhi + z * sB + (long)nT * ldb;
    const __half* Bl = Blo + z * sB + (long)nT * ldb;
    const int NC = K >> 6;

    tileA64(Ah, lda, sb,          tid);
    tileA64(Al, lda, sb + 8192,   tid);
    tileB128(Bh, ldb, sb + 16384, tid);
    tileB128(Bl, ldb, sb + 32768, tid);
    CP_COMMIT();

    float acc[2][4][4] = {};
    uint32_t acc16[2][4][2] = {};                    // f16 correction acc
    const int aRow = lane & 15;
    const int aColB = (lane >> 4) * 16;
    const int bRowP = ((lane >> 4) & 1) * 8 + (lane & 7);
    const int bColB = ((lane >> 3) & 1) * 16;

    for (int c = 0; c < NC; c++) {
        if (c + 1 < NC) {
            const uint32_t o1 = sb + ((c + 1) & 1) * 49152;
            const int k1 = (c + 1) * 64;
            tileA64(Ah + k1, lda, o1,          tid);
            tileA64(Al + k1, lda, o1 + 8192,   tid);
            tileB128(Bh + k1, ldb, o1 + 16384, tid);
            tileB128(Bl + k1, ldb, o1 + 32768, tid);
            CP_COMMIT();
            CP_WAIT1();
        } else {
            CP_WAIT0();
        }
        __syncthreads();

        const uint32_t o = sb + (c & 1) * 49152;
        #pragma unroll
        for (int ks = 0; ks < 4; ks++) {
            const int kb = ks * 32;
            uint32_t rah[2][4], ral[2][4], rbh[4][2], rbl[4][2];
            #pragma unroll
            for (int mi = 0; mi < 2; mi++) {
                uint32_t off = swz((uint32_t)(wM * 32 + mi * 16 + aRow) * 128 + kb + aColB);
                LDSM_X4(rah[mi][0], rah[mi][1], rah[mi][2], rah[mi][3], o + off);
                LDSM_X4(ral[mi][0], ral[mi][1], ral[mi][2], ral[mi][3], o + 8192 + off);
            }
            #pragma unroll
            for (int p = 0; p < 2; p++) {
                uint32_t off = swz((uint32_t)(wN * 32 + p * 16 + bRowP) * 128 + kb + bColB);
                LDSM_X4(rbh[2 * p][0], rbh[2 * p][1], rbh[2 * p + 1][0], rbh[2 * p + 1][1],
                        o + 16384 + off);
                LDSM_X4(rbl[2 * p][0], rbl[2 * p][1], rbl[2 * p + 1][0], rbl[2 * p + 1][1],
                        o + 32768 + off);
            }
            #pragma unroll
            for (int mi = 0; mi < 2; mi++)
                #pragma unroll
                for (int ni = 0; ni < 4; ni++) {
                    MMA_F16(acc[mi][ni], rah[mi], rbh[ni]);      // HH -> f32
                    MMA_F16ACC(acc16[mi][ni], rah[mi], rbl[ni]); // HL -> f16
                    MMA_F16ACC(acc16[mi][ni], ral[mi], rbh[ni]); // LH -> f16
                }
        }
        __syncthreads();
    }

    // merge f16 correction acc into f32 acc
    #pragma unroll
    for (int mi = 0; mi < 2; mi++)
        #pragma unroll
        for (int ni = 0; ni < 4; ni++) {
            __half2 p0 = *(__half2*)&acc16[mi][ni][0];
            __half2 p1 = *(__half2*)&acc16[mi][ni][1];
            acc[mi][ni][0] += __low2float(p0);
            acc[mi][ni][1] += __high2float(p0);
            acc[mi][ni][2] += __low2float(p1);
            acc[mi][ni][3] += __high2float(p1);
        }

    const int rBase = mT + wM * 32 + (lane >> 2);
    const int cBase = nT + wN * 32 + (lane & 3) * 2;

    if (EM == 1) {
        #pragma unroll
        for (int mi = 0; mi < 2; mi++)
            #pragma unroll
            for (int ni = 0; ni < 4; ni++) {
                const int r0 = rBase + mi * 16;
                const int c0 = cBase + ni * 8;
                float* p = acc[mi][ni];
                #pragma unroll
                for (int hh = 0; hh < 2; hh++) {
                    __half h0, l0, h1, l1;
                    split1h(p[hh * 2 + 0], h0, l0);
                    split1h(p[hh * 2 + 1], h1, l1);
                    uint32_t ph = ((uint32_t)*(uint16_t*)&h1 << 16) | *(uint16_t*)&h0;
                    uint32_t pl = ((uint32_t)*(uint16_t*)&l1 << 16) | *(uint16_t*)&l0;
                    size_t idx = z * sC + (size_t)(r0 + hh * 8) * ldc + c0;
                    *(uint32_t*)(Chi + idx) = ph;
                    *(uint32_t*)(Clo + idx) = pl;
                }
            }
    }

    if (EM == 3) {
        float* sred = (float*)smem;          // [2][128] maxes, [2][128] sums at +256
        #pragma unroll
        for (int ni = 0; ni < 4; ni++)
            #pragma unroll
            for (int q = 0; q < 2; q++) {
                float m = -1e30f;
                #pragma unroll
                for (int mi = 0; mi < 2; mi++)
                    m = fmaxf(m, fmaxf(acc[mi][ni][q], acc[mi][ni][q + 2]));
                #pragma unroll
                for (int mk = 4; mk <= 16; mk <<= 1)
                    m = fmaxf(m, __shfl_xor_sync(0xFFFFFFFFu, m, mk));
                if (lane < 4)
                    sred[wM * 128 + wN * 32 + ni * 8 + (lane & 3) * 2 + q] = m;
            }
        __syncthreads();
        #pragma unroll
        for (int ni = 0; ni < 4; ni++) {
            const int colb = wN * 32 + ni * 8 + (lane & 3) * 2;
            const float fm0 = fmaxf(sred[colb],     sred[128 + colb]);
            const float fm1 = fmaxf(sred[colb + 1], sred[128 + colb + 1]);
            float s0 = 0.f, s1 = 0.f;
            #pragma unroll
            for (int mi = 0; mi < 2; mi++) {
                float* p = acc[mi][ni];
                float u0 = __expf(p[0] - fm0), u1 = __expf(p[1] - fm1);
                float u2 = __expf(p[2] - fm0), u3 = __expf(p[3] - fm1);
                s0 += u0 + u2; s1 += u1 + u3;
                const int r0 = rBase + mi * 16;
                const int c0 = cBase + ni * 8;
                *(uint32_t*)(Chi + z * sC + (size_t)r0 * ldc + c0) = pack2h(u0, u1);
                *(uint32_t*)(Chi + z * sC + (size_t)(r0 + 8) * ldc + c0) = pack2h(u2, u3);
            }
            #pragma unroll
            for (int mk = 4; mk <= 16; mk <<= 1) {
                s0 += __shfl_xor_sync(0xFFFFFFFFu, s0, mk);
                s1 += __shfl_xor_sync(0xFFFFFFFFu, s1, mk);
            }
            if (lane < 4) {
                sred[256 + wM * 128 + colb] = s0;
                sred[256 + wM * 128 + colb + 1] = s1;
            }
        }
        __syncthreads();
        if (tid < 128) {
            float fm = fmaxf(sred[tid], sred[128 + tid]);
            float s = sred[256 + tid] + sred[384 + tid];
            size_t idx = ((size_t)z * 32 + blockIdx.y) * L_ + nT + tid;
            Pmax[idx] = fm;
            Psum[idx] = s;
        }
    }
}

// ======================= 1-pass fp16 NT GEMM (128x128) =====================
// D = A * B^T, both single fp16; A produced in-kernel. 256 thr, 8 warps
// (2Mx4N, warp tile 64x32). Stage 32KB {A16K, B16K} x2 = 64KB.
// AM 1: A = u * Fac[tile64, j] | AM 2: A = cat(g, C, g*C)
// EM 0: fp32 store | EM 2: bias + relu fp32
static constexpr int GEMM1_SMEM = 2 * 32768;

template <int AM, int EM>
__global__ __launch_bounds__(256, 2)
void gemm1p(const __half* __restrict__ U, const float* __restrict__ Fac,
            const float* __restrict__ Af1, const float* __restrict__ Af2,
            const __half* __restrict__ Bg,
            float* __restrict__ Cf, const float* __restrict__ bias,
            int K, int ldaF, int ldb, int ldc, long sA, long sB, long sC)
{
    extern __shared__ char smem[];
    const uint32_t sb = smem_u32(smem);
    const int tid = threadIdx.x;
    const int lane = tid & 31, wid = tid >> 5;
    const int wM = wid >> 2, wN = wid & 3;           // 2 x 4 warp grid
    const int mT = blockIdx.y * 128, nT = blockIdx.x * 128;
    const long z = blockIdx.z;

    const __half* Bp = Bg + z * sB + (long)nT * ldb;
    const int NC = K >> 6;

    const int c4 = tid & 15;
    const int rA = tid >> 4;                         // 0..15, rows rA + s*16
    uint2 ua[8];
    const __half* Ug = (AM == 1) ? (U + z * sA + (size_t)mT * ldaF) : nullptr;
    const float* Facp = (AM == 1) ? (Fac + ((size_t)z * 32 + blockIdx.y * 2) * L_) : nullptr;

    if (AM == 1) {
        #pragma unroll
        for (int s = 0; s < 8; s++)
            ua[s] = *(const uint2*)(Ug + (size_t)(rA + s * 16) * ldaF + c4 * 4);
    }
    tileB128(Bp, ldb, sb + 16384, tid);
    CP_COMMIT();

    float acc[4][4][4] = {};
    const int aRow = lane & 15;
    const int aColB = (lane >> 4) * 16;
    const int bRowP = ((lane >> 4) & 1) * 8 + (lane & 7);
    const int bColB = ((lane >> 3) & 1) * 16;

    for (int c = 0; c < NC; c++) {
        const int buf = c & 1;

        // ---- produce A(c) into buf ----
        if (AM == 1) {
            const int k0 = c * 64;
            float4 fv0 = *(const float4*)(Facp + k0 + c4 * 4);
            float4 fv1 = *(const float4*)(Facp + L_ + k0 + c4 * 4);
            #pragma unroll
            for (int s = 0; s < 8; s++) {
                const float4 fv = (s < 4) ? fv0 : fv1;
                const __half* uh = (const __half*)&ua[s];
                float4 v = make_float4(__half2float(uh[0]) * fv.x,
                                       __half2float(uh[1]) * fv.y,
                                       __half2float(uh[2]) * fv.z,
                                       __half2float(uh[3]) * fv.w);
                uint32_t off = swz((uint32_t)(rA + s * 16) * 128 + c4 * 8);
                *(uint2*)(smem + buf * 32768 + off) = pack4h(v);
            }
        } else {
            const int k0 = c * 64;
            const int seg = k0 >> 8;
            const int hc = (k0 & 255) + c4 * 4;
            #pragma unroll
            for (int s = 0; s < 8; s++) {
                const size_t mrow = (size_t)(mT + rA + s * 16);
                float4 v;
                if (seg == 0) v = *(const float4*)(Af1 + mrow * ldaF + hc);
                else if (seg == 1) v = *(const float4*)(Af2 + mrow * ldaF + hc);
                else {
                    float4 g4 = *(const float4*)(Af1 + mrow * ldaF + hc);
                    float4 cc = *(const float4*)(Af2 + mrow * ldaF + hc);
                    v = make_float4(g4.x * cc.x, g4.y * cc.y, g4.z * cc.z, g4.w * cc.w);
                }
                uint32_t off = swz((uint32_t)(rA + s * 16) * 128 + c4 * 8);
                *(uint2*)(smem + buf * 32768 + off) = pack4h(v);
            }
        }

        // ---- stage chunk c+1 ----
        if (c + 1 < NC) {
            const uint32_t o1 = sb + ((c + 1) & 1) * 32768;
            const int k1 = (c + 1) * 64;
            if (AM == 1) {
                #pragma unroll
                for (int s = 0; s < 8; s++)
                    ua[s] = *(const uint2*)(Ug + (size_t)(rA + s * 16) * ldaF + k1 + c4 * 4);
            }
            tileB128(Bp + k1, ldb, o1 + 16384, tid);
            CP_COMMIT();
            CP_WAIT1();
        } else {
            CP_WAIT0();
        }
        __syncthreads();

        const uint32_t o = sb + buf * 32768;
        #pragma unroll
        for (int ks = 0; ks < 4; ks++) {
            const int kb = ks * 32;
            uint32_t rah[4][4], rbh[4][2];
            #pragma unroll
            for (int mi = 0; mi < 4; mi++) {
                uint32_t off = swz((uint32_t)(wM * 64 + mi * 16 + aRow) * 128 + kb + aColB);
                LDSM_X4(rah[mi][0], rah[mi][1], rah[mi][2], rah[mi][3], o + off);
            }
            #pragma unroll
            for (int p = 0; p < 2; p++) {
                uint32_t off = swz((uint32_t)(wN * 32 + p * 16 + bRowP) * 128 + kb + bColB);
                LDSM_X4(rbh[2 * p][0], rbh[2 * p][1], rbh[2 * p + 1][0], rbh[2 * p + 1][1],
                        o + 16384 + off);
            }
            #pragma unroll
            for (int mi = 0; mi < 4; mi++)
                #pragma unroll
                for (int ni = 0; ni < 4; ni++)
                    MMA_F16(acc[mi][ni], rah[mi], rbh[ni]);
        }
        __syncthreads();
    }

    const int rBase = mT + wM * 64 + (lane >> 2);
    const int cBase = nT + wN * 32 + (lane & 3) * 2;
    #pragma unroll
    for (int mi = 0; mi < 4; mi++)
        #pragma unroll
        for (int ni = 0; ni < 4; ni++) {
            const int r0 = rBase + mi * 16;
            const int c0 = cBase + ni * 8;
            float* p = acc[mi][ni];
            if (EM == 0) {
                float* dst = Cf + z * sC;
                *(float2*)(dst + (size_t)r0 * ldc + c0) = make_float2(p[0], p[1]);
                *(float2*)(dst + (size_t)(r0 + 8) * ldc + c0) = make_float2(p[2], p[3]);
            } else {
                float2 bv = *(const float2*)(bias + c0);
                float* dst = Cf + z * sC;
                *(float2*)(dst + (size_t)r0 * ldc + c0) =
                    make_float2(fmaxf(p[0] + bv.x, 0.f), fmaxf(p[1] + bv.y, 0.f));
                *(float2*)(dst + (size_t)(r0 + 8) * ldc + c0) =
                    make_float2(fmaxf(p[2] + bv.x, 0.f), fmaxf(p[3] + bv.y, 0.f));
            }
        }
}

// ======================= prep / softmax kernels ============================
__global__ void split_k(const float* __restrict__ x, __half* __restrict__ hi,
                        __half* __restrict__ lo, int n4)
{
    for (int i = blockIdx.x * blockDim.x + threadIdx.x; i < n4; i += gridDim.x * blockDim.x) {
        float4 v = ((const float4*)x)[i];
        uint2 h, l; pack_split4h(v, h, l);
        ((uint2*)hi)[i] = h;
        ((uint2*)lo)[i] = l;
    }
}

__global__ void convert_k(const float* __restrict__ x, __half* __restrict__ y, int n4)
{
    for (int i = blockIdx.x * blockDim.x + threadIdx.x; i < n4; i += gridDim.x * blockDim.x) {
        float4 v = ((const float4*)x)[i];
        ((uint2*)y)[i] = pack4h(v);
    }
}

// gTs[b, h, j] = ID[b,j] * g[b, j, h], single fp16
__global__ void transpose_scale(const float* __restrict__ G, const float* __restrict__ ID,
                                __half* __restrict__ T)
{
    __shared__ float t[32][33];
    const int j0 = blockIdx.x * 32, h0 = blockIdx.y * 32, b = blockIdx.z;
    const float* Gb = G + (size_t)b * L_ * H_;
    #pragma unroll
    for (int r = 0; r < 4; r++) {
        int row = threadIdx.y + r * 8;
        t[row][threadIdx.x] = Gb[(size_t)(j0 + row) * H_ + h0 + threadIdx.x]
                              * ID[b * L_ + j0 + row];
    }
    __syncthreads();
    __half* Tb = T + (size_t)b * H_ * L_;
    #pragma unroll
    for (int r = 0; r < 4; r++) {
        int hr = threadIdx.y + r * 8;
        Tb[(size_t)(h0 + hr) * L_ + j0 + threadIdx.x] = __float2half_rn(t[threadIdx.x][hr]);
    }
}

// combine 32 per-tile partials per column -> ID = 1/D, Fac[t] = exp(pm[t]-M)
__global__ void reduce_stats(const float* __restrict__ Pmax, const float* __restrict__ Psum,
                             float* __restrict__ IDo, float* __restrict__ Fac)
{
    const int idx = blockIdx.x * blockDim.x + threadIdx.x;
    const size_t base = ((size_t)(idx >> 11) * 32) * L_ + (idx & (L_ - 1));
    float M = -1e30f;
    float pm[32];
    #pragma unroll
    for (int t = 0; t < 32; t++) {
        pm[t] = Pmax[base + (size_t)t * L_];
        M = fmaxf(M, pm[t]);
    }
    float D = 0.f;
    #pragma unroll
    for (int t = 0; t < 32; t++) {
        float e = __expf(pm[t] - M);
        D += Psum[base + (size_t)t * L_] * e;
        Fac[base + (size_t)t * L_] = e;
    }
    IDo[idx] = 1.0f / D;
}

// ===========================================================================
extern "C" void kernel_launch(void* const* d_in, const int* in_sizes, int n_in,
                              void* d_out, int out_size)
{
    const float* g     = (const float*)d_in[0];
    const float* WP    = (const float*)d_in[1];
    const float* W_out = (const float*)d_in[2];
    const float* b_out = (const float*)d_in[3];
    float* out = (float*)d_out;

    float *C, *ID, *Pm, *Ps, *Fc;
    __half *U, *gHi, *gLo, *gTs, *WhHi, *WhLo, *WPHi, *WPLo, *Wo16;
    cudaGetSymbolAddress((void**)&U, d_U);
    cudaGetSymbolAddress((void**)&C, d_C);
    cudaGetSymbolAddress((void**)&ID, d_ID);
    cudaGetSymbolAddress((void**)&Pm, d_Pmax);
    cudaGetSymbolAddress((void**)&Ps, d_Psum);
    cudaGetSymbolAddress((void**)&Fc, d_Fac);
    cudaGetSymbolAddress((void**)&gHi, d_gHi);   cudaGetSymbolAddress((void**)&gLo, d_gLo);
    cudaGetSymbolAddress((void**)&gTs, d_gTs);
    cudaGetSymbolAddress((void**)&WhHi, d_WhHi); cudaGetSymbolAddress((void**)&WhLo, d_WhLo);
    cudaGetSymbolAddress((void**)&WPHi, d_WPHi); cudaGetSymbolAddress((void**)&WPLo, d_WPLo);
    cudaGetSymbolAddress((void**)&Wo16, d_Wo16);

    cudaFuncSetAttribute(gemm3p<1>, cudaFuncAttributeMaxDynamicSharedMemorySize, GEMM3_SMEM);
    cudaFuncSetAttribute(gemm3p<3>, cudaFuncAttributeMaxDynamicSharedMemorySize, GEMM3_SMEM);
    cudaFuncSetAttribute(gemm1p<1,0>, cudaFuncAttributeMaxDynamicSharedMemorySize, GEMM1_SMEM);
    cudaFuncSetAttribute(gemm1p<2,2>, cudaFuncAttributeMaxDynamicSharedMemorySize, GEMM1_SMEM);

    // 0) splits / converts
    split_k<<<2048, 256>>>(g, gHi, gLo, B_ * L_ * H_ / 4);
    split_k<<<64, 256>>>(WP, WPHi, WPLo, H_ * H_ / 4);
    convert_k<<<96, 256>>>(W_out, Wo16, H_ * 3 * H_ / 4);

    // 1) Wh = g @ WP^T  (HH f32 + HL/LH f16-acc, split-fp16 out)
    gemm3p<1><<<dim3(2, 256, 1), 256, GEMM3_SMEM>>>(
        gHi, gLo, WPHi, WPLo, WhHi, WhLo, nullptr, nullptr,
        H_, H_, H_, H_, 0, 0, 0);

    // 2) u[b] = exp(Wh[b] @ g[b]^T - m_tile64) fp16 + per-tile column stats
    gemm3p<3><<<dim3(16, 32, B_), 256, GEMM3_SMEM>>>(
        WhHi, WhLo, gHi, gLo, U, nullptr, Pm, Ps,
        H_, H_, H_, L_, (long)L_ * H_, (long)L_ * H_, (long)L_ * L_);

    // 3) combine partials -> ID, Fac
    reduce_stats<<<(B_ * L_) / 256, 256>>>(Pm, Ps, ID, Fc);

    // 4) gTs = (ID_j * g)^T single fp16
    transpose_scale<<<dim3(L_ / 32, H_ / 32, B_), dim3(32, 8)>>>(g, ID, gTs);

    // 5) c[b] = (u * Fac) @ gTs^T  (1-pass, A in-kernel)
    gemm1p<1,0><<<dim3(2, 16, B_), 256, GEMM1_SMEM>>>(
        U, Fc, nullptr, nullptr, gTs, C, nullptr,
        L_, L_, L_, H_, (long)L_ * L_, (long)H_ * L_, (long)L_ * H_);

    // 6) out = relu(cat(g, c, g*c) @ Wo16^T + b)  (1-pass, A built in-kernel)
    gemm1p<2,2><<<dim3(2, 128, 1), 256, GEMM1_SMEM>>>(
        nullptr, nullptr, g, C, Wo16, out, b_out,
        3 * H_, H_, 3 * H_, H_, 0, 0, 0);
}

// round 16
// speedup vs baseline: 1.0288x; 1.0273x over previous
#include <cuda_runtime.h>
#include <cuda_fp16.h>
#include <cstdint>
#include <math.h>

#define B_ 8
#define L_ 2048
#define H_ 256

// ======================= PTX helpers (baseline ISA only) ===================
__device__ __forceinline__ uint32_t smem_u32(const void* p) {
    uint32_t a;
    asm("{ .reg .u64 t; cvta.to.shared.u64 t, %1; cvt.u32.u64 %0, t; }" : "=r"(a) : "l"(p));
    return a;
}
#define CP_ASYNC16(dst, src) \
    asm volatile("cp.async.cg.shared.global [%0], [%1], 16;" :: "r"(dst), "l"(src) : "memory")
#define CP_COMMIT() asm volatile("cp.async.commit_group;" ::: "memory")
#define CP_WAIT1()  asm volatile("cp.async.wait_group 1;" ::: "memory")
#define CP_WAIT0()  asm volatile("cp.async.wait_group 0;" ::: "memory")

#define LDSM_X4(r0, r1, r2, r3, a) \
    asm volatile("ldmatrix.sync.aligned.m8n8.x4.shared.b16 {%0,%1,%2,%3}, [%4];" \
        : "=r"(r0), "=r"(r1), "=r"(r2), "=r"(r3) : "r"(a))

#define MMA_F16(d, a, b) \
    asm volatile("mma.sync.aligned.m16n8k16.row.col.f32.f16.f16.f32 " \
        "{%0,%1,%2,%3}, {%4,%5,%6,%7}, {%8,%9}, {%0,%1,%2,%3};" \
        : "+f"((d)[0]), "+f"((d)[1]), "+f"((d)[2]), "+f"((d)[3]) \
        : "r"((a)[0]), "r"((a)[1]), "r"((a)[2]), "r"((a)[3]), "r"((b)[0]), "r"((b)[1]))

__device__ __forceinline__ uint32_t swz(uint32_t o) { return o ^ ((o >> 3) & 0x70); }

// ======================= scratch (device globals) ==========================
__device__ __half  d_U[(size_t)B_ * L_ * L_];        // exp(s - m_tile64), 64 MB
__device__ __half  d_gHi[B_ * L_ * H_], d_gLo[B_ * L_ * H_];
__device__ __half  d_gTs[B_ * H_ * L_];              // ID-scaled g^T, single fp16
__device__ __half  d_WhHi[B_ * L_ * H_], d_WhLo[B_ * L_ * H_];
__device__ __half  d_WPHi[H_ * H_], d_WPLo[H_ * H_];
__device__ __half  d_Wo16[H_ * 3 * H_];              // W_out single fp16
__device__ float   d_C[B_ * L_ * H_];
__device__ float   d_ID[B_ * L_];
__device__ float   d_Pmax[B_ * 32 * L_], d_Psum[B_ * 32 * L_];     // per-64-row-tile
__device__ float   d_Fac[B_ * 32 * L_];              // exp(m_tile64 - M_global)

__device__ __forceinline__ void split1h(float x, __half& h, __half& l) {
    h = __float2half_rn(x);
    l = __float2half_rn(x - __half2float(h));
}
__device__ __forceinline__ void pack_split4h(float4 v, uint2& hi, uint2& lo) {
    __half h[4], l[4];
    split1h(v.x, h[0], l[0]); split1h(v.y, h[1], l[1]);
    split1h(v.z, h[2], l[2]); split1h(v.w, h[3], l[3]);
    hi = *(uint2*)h; lo = *(uint2*)l;
}
__device__ __forceinline__ uint2 pack4h(float4 v) {
    __half h[4];
    h[0] = __float2half_rn(v.x); h[1] = __float2half_rn(v.y);
    h[2] = __float2half_rn(v.z); h[3] = __float2half_rn(v.w);
    return *(uint2*)h;
}
__device__ __forceinline__ uint32_t pack2h(float a, float b) {
    __half h0 = __float2half_rn(a), h1 = __float2half_rn(b);
    return ((uint32_t)*(uint16_t*)&h1 << 16) | *(uint16_t*)&h0;
}

// ---- smem tile loaders (K-chunk 64 halves = 128B rows, SW128) ----
__device__ __forceinline__ void tileA64(const __half* __restrict__ src, int ld,
                                        uint32_t dstBase, int tid) {
    #pragma unroll
    for (int s = 0; s < 2; s++) {
        int slot = tid + s * 256;
        int row = slot >> 3;
        int cb = (slot & 7) * 16;
        CP_ASYNC16(dstBase + swz(row * 128 + cb), (const char*)src + (size_t)row * ld * 2 + cb);
    }
}
__device__ __forceinline__ void tileB128(const __half* __restrict__ src, int ld,
                                         uint32_t dstBase, int tid) {
    #pragma unroll
    for (int s = 0; s < 4; s++) {
        int slot = tid + s * 256;
        int row = slot >> 3;
        int cb = (slot & 7) * 16;
        CP_ASYNC16(dstBase + swz(row * 128 + cb), (const char*)src + (size_t)row * ld * 2 + cb);
    }
}

// ======================= 3-pass split-fp16 NT GEMM (64x128) ================
// D = (Ah+Al)(Bh+Bl)^T via HH+HL+LH. 256 thr, 8 warps (2M x 4N, warp tile
// 32x32), K-chunk 64, 2-stage cp.async. Stage 48KB x2 = 96KB -> 2 CTAs/SM.
// EM 1: split-fp16 store (grid-mapped tiles)
// EM 3: u = exp(D - m_tile64col) fp16 + col stats; PERSISTENT tile loop
static constexpr int GEMM3_SMEM = 2 * 49152;
static constexpr int PERSIST_GRID = 304;             // 2 CTAs x 152 SMs
static constexpr int S_TILES = 16 * 32 * B_;         // 4096

template <int EM>
__global__ __launch_bounds__(256, 2)
void gemm3p(const __half* __restrict__ Ahi, const __half* __restrict__ Alo,
            const __half* __restrict__ Bhi, const __half* __restrict__ Blo,
            __half* __restrict__ Chi, __half* __restrict__ Clo,
            float* __restrict__ Pmax, float* __restrict__ Psum,
            int K, int lda, int ldb, int ldc, long sA, long sB, long sC)
{
    extern __shared__ char smem[];
    const uint32_t sb = smem_u32(smem);
    const int tid = threadIdx.x;
    const int lane = tid & 31, wid = tid >> 5;
    const int wM = wid >> 2, wN = wid & 3;           // 2 x 4 warp grid
    const int NC = K >> 6;
    const int aRow = lane & 15;
    const int aColB = (lane >> 4) * 16;
    const int bRowP = ((lane >> 4) & 1) * 8 + (lane & 7);
    const int bColB = ((lane >> 3) & 1) * 16;

    int tile = (EM == 3) ? blockIdx.x : 0;
    while (true) {
        int mT, nT; long z;
        if (EM == 3) {
            z = tile >> 9;
            int rem = tile & 511;
            mT = (rem >> 4) << 6;      // 64-row tiles
            nT = (rem & 15) << 7;      // 128-col tiles
        } else {
            mT = blockIdx.y * 64; nT = blockIdx.x * 128; z = blockIdx.z;
        }

        const __half* Ah = Ahi + z * sA + (long)mT * lda;
        const __half* Al = Alo + z * sA + (long)mT * lda;
        const __half* Bh = Bhi + z * sB + (long)nT * ldb;
        const __half* Bl = Blo + z * sB + (long)nT * ldb;

        tileA64(Ah, lda, sb,          tid);
        tileA64(Al, lda, sb + 8192,   tid);
        tileB128(Bh, ldb, sb + 16384, tid);
        tileB128(Bl, ldb, sb + 32768, tid);
        CP_COMMIT();

        float acc[2][4][4] = {};

        for (int c = 0; c < NC; c++) {
            if (c + 1 < NC) {
                const uint32_t o1 = sb + ((c + 1) & 1) * 49152;
                const int k1 = (c + 1) * 64;
                tileA64(Ah + k1, lda, o1,          tid);
                tileA64(Al + k1, lda, o1 + 8192,   tid);
                tileB128(Bh + k1, ldb, o1 + 16384, tid);
                tileB128(Bl + k1, ldb, o1 + 32768, tid);
                CP_COMMIT();
                CP_WAIT1();
            } else {
                CP_WAIT0();
            }
            __syncthreads();

            const uint32_t o = sb + (c & 1) * 49152;
            #pragma unroll
            for (int ks = 0; ks < 4; ks++) {
                const int kb = ks * 32;
                uint32_t rah[2][4], ral[2][4], rbh[4][2], rbl[4][2];
                #pragma unroll
                for (int mi = 0; mi < 2; mi++) {
                    uint32_t off = swz((uint32_t)(wM * 32 + mi * 16 + aRow) * 128 + kb + aColB);
                    LDSM_X4(rah[mi][0], rah[mi][1], rah[mi][2], rah[mi][3], o + off);
                    LDSM_X4(ral[mi][0], ral[mi][1], ral[mi][2], ral[mi][3], o + 8192 + off);
                }
                #pragma unroll
                for (int p = 0; p < 2; p++) {
                    uint32_t off = swz((uint32_t)(wN * 32 + p * 16 + bRowP) * 128 + kb + bColB);
                    LDSM_X4(rbh[2 * p][0], rbh[2 * p][1], rbh[2 * p + 1][0], rbh[2 * p + 1][1],
                            o + 16384 + off);
                    LDSM_X4(rbl[2 * p][0], rbl[2 * p][1], rbl[2 * p + 1][0], rbl[2 * p + 1][1],
                            o + 32768 + off);
                }
                #pragma unroll
                for (int mi = 0; mi < 2; mi++)
                    #pragma unroll
                    for (int ni = 0; ni < 4; ni++) {
                        MMA_F16(acc[mi][ni], rah[mi], rbh[ni]);
                        MMA_F16(acc[mi][ni], rah[mi], rbl[ni]);
                        MMA_F16(acc[mi][ni], ral[mi], rbh[ni]);
                    }
            }
            __syncthreads();
        }

        const int rBase = mT + wM * 32 + (lane >> 2);
        const int cBase = nT + wN * 32 + (lane & 3) * 2;

        if (EM == 1) {
            #pragma unroll
            for (int mi = 0; mi < 2; mi++)
                #pragma unroll
                for (int ni = 0; ni < 4; ni++) {
                    const int r0 = rBase + mi * 16;
                    const int c0 = cBase + ni * 8;
                    float* p = acc[mi][ni];
                    #pragma unroll
                    for (int hh = 0; hh < 2; hh++) {
                        __half h0, l0, h1, l1;
                        split1h(p[hh * 2 + 0], h0, l0);
                        split1h(p[hh * 2 + 1], h1, l1);
                        uint32_t ph = ((uint32_t)*(uint16_t*)&h1 << 16) | *(uint16_t*)&h0;
                        uint32_t pl = ((uint32_t)*(uint16_t*)&l1 << 16) | *(uint16_t*)&l0;
                        size_t idx = z * sC + (size_t)(r0 + hh * 8) * ldc + c0;
                        *(uint32_t*)(Chi + idx) = ph;
                        *(uint32_t*)(Clo + idx) = pl;
                    }
                }
        }

        if (EM == 3) {
            float* sred = (float*)smem;      // [2][128] maxes, [2][128] sums at +256
            #pragma unroll
            for (int ni = 0; ni < 4; ni++)
                #pragma unroll
                for (int q = 0; q < 2; q++) {
                    float m = -1e30f;
                    #pragma unroll
                    for (int mi = 0; mi < 2; mi++)
                        m = fmaxf(m, fmaxf(acc[mi][ni][q], acc[mi][ni][q + 2]));
                    #pragma unroll
                    for (int mk = 4; mk <= 16; mk <<= 1)
                        m = fmaxf(m, __shfl_xor_sync(0xFFFFFFFFu, m, mk));
                    if (lane < 4)
                        sred[wM * 128 + wN * 32 + ni * 8 + (lane & 3) * 2 + q] = m;
                }
            __syncthreads();
            #pragma unroll
            for (int ni = 0; ni < 4; ni++) {
                const int colb = wN * 32 + ni * 8 + (lane & 3) * 2;
                const float fm0 = fmaxf(sred[colb],     sred[128 + colb]);
                const float fm1 = fmaxf(sred[colb + 1], sred[128 + colb + 1]);
                float s0 = 0.f, s1 = 0.f;
                #pragma unroll
                for (int mi = 0; mi < 2; mi++) {
                    float* p = acc[mi][ni];
                    float u0 = __expf(p[0] - fm0), u1 = __expf(p[1] - fm1);
                    float u2 = __expf(p[2] - fm0), u3 = __expf(p[3] - fm1);
                    s0 += u0 + u2; s1 += u1 + u3;
                    const int r0 = rBase + mi * 16;
                    const int c0 = cBase + ni * 8;
                    *(uint32_t*)(Chi + z * sC + (size_t)r0 * ldc + c0) = pack2h(u0, u1);
                    *(uint32_t*)(Chi + z * sC + (size_t)(r0 + 8) * ldc + c0) = pack2h(u2, u3);
                }
                #pragma unroll
                for (int mk = 4; mk <= 16; mk <<= 1) {
                    s0 += __shfl_xor_sync(0xFFFFFFFFu, s0, mk);
                    s1 += __shfl_xor_sync(0xFFFFFFFFu, s1, mk);
                }
                if (lane < 4) {
                    sred[256 + wM * 128 + colb] = s0;
                    sred[256 + wM * 128 + colb + 1] = s1;
                }
            }
            __syncthreads();
            if (tid < 128) {
                float fm = fmaxf(sred[tid], sred[128 + tid]);
                float s = sred[256 + tid] + sred[384 + tid];
                size_t idx = ((size_t)z * 32 + (mT >> 6)) * L_ + nT + tid;
                Pmax[idx] = fm;
                Psum[idx] = s;
            }
        }

        if (EM == 3) {
            tile += PERSIST_GRID;
            if (tile >= S_TILES) break;
            __syncthreads();                 // sred reads done before next prologue
        } else {
            break;
        }
    }
}

// ======================= 1-pass fp16 NT GEMM (128x128) =====================
// D = A * B^T, both single fp16; A produced in-kernel. 256 thr, 8 warps
// (2Mx4N, warp tile 64x32). Stage 32KB {A16K, B16K} x2 = 64KB.
// AM 1: A = u * Fac[tile64, j] (hmul2) | AM 2: A = cat(g, C, g*C)
// EM 0: fp32 store | EM 2: bias + relu fp32
static constexpr int GEMM1_SMEM = 2 * 32768;

template <int AM, int EM>
__global__ __launch_bounds__(256, 2)
void gemm1p(const __half* __restrict__ U, const float* __restrict__ Fac,
            const float* __restrict__ Af1, const float* __restrict__ Af2,
            const __half* __restrict__ Bg,
            float* __restrict__ Cf, const float* __restrict__ bias,
            int K, int ldaF, int ldb, int ldc, long sA, long sB, long sC)
{
    extern __shared__ char smem[];
    const uint32_t sb = smem_u32(smem);
    const int tid = threadIdx.x;
    const int lane = tid & 31, wid = tid >> 5;
    const int wM = wid >> 2, wN = wid & 3;           // 2 x 4 warp grid
    const int mT = blockIdx.y * 128, nT = blockIdx.x * 128;
    const long z = blockIdx.z;

    const __half* Bp = Bg + z * sB + (long)nT * ldb;
    const int NC = K >> 6;

    const int c4 = tid & 15;
    const int rA = tid >> 4;                         // 0..15, rows rA + s*16
    uint2 ua[8];
    const __half* Ug = (AM == 1) ? (U + z * sA + (size_t)mT * ldaF) : nullptr;
    const float* Facp = (AM == 1) ? (Fac + ((size_t)z * 32 + blockIdx.y * 2) * L_) : nullptr;

    if (AM == 1) {
        #pragma unroll
        for (int s = 0; s < 8; s++)
            ua[s] = *(const uint2*)(Ug + (size_t)(rA + s * 16) * ldaF + c4 * 4);
    }
    tileB128(Bp, ldb, sb + 16384, tid);
    CP_COMMIT();

    float acc[4][4][4] = {};
    const int aRow = lane & 15;
    const int aColB = (lane >> 4) * 16;
    const int bRowP = ((lane >> 4) & 1) * 8 + (lane & 7);
    const int bColB = ((lane >> 3) & 1) * 16;

    for (int c = 0; c < NC; c++) {
        const int buf = c & 1;

        // ---- produce A(c) into buf ----
        if (AM == 1) {
            const int k0 = c * 64;
            float4 fv0 = *(const float4*)(Facp + k0 + c4 * 4);
            float4 fv1 = *(const float4*)(Facp + L_ + k0 + c4 * 4);
            __half2 fA01 = __floats2half2_rn(fv0.x, fv0.y);
            __half2 fA23 = __floats2half2_rn(fv0.z, fv0.w);
            __half2 fB01 = __floats2half2_rn(fv1.x, fv1.y);
            __half2 fB23 = __floats2half2_rn(fv1.z, fv1.w);
            #pragma unroll
            for (int s = 0; s < 8; s++) {
                const __half2* uh = (const __half2*)&ua[s];
                __half2 f01 = (s < 4) ? fA01 : fB01;
                __half2 f23 = (s < 4) ? fA23 : fB23;
                uint2 w;
                *(__half2*)&w.x = __hmul2(uh[0], f01);
                *(__half2*)&w.y = __hmul2(uh[1], f23);
                uint32_t off = swz((uint32_t)(rA + s * 16) * 128 + c4 * 8);
                *(uint2*)(smem + buf * 32768 + off) = w;
            }
        } else {
            const int k0 = c * 64;
            const int seg = k0 >> 8;
            const int hc = (k0 & 255) + c4 * 4;
            #pragma unroll
            for (int s = 0; s < 8; s++) {
                const size_t mrow = (size_t)(mT + rA + s * 16);
                float4 v;
                if (seg == 0) v = *(const float4*)(Af1 + mrow * ldaF + hc);
                else if (seg == 1) v = *(const float4*)(Af2 + mrow * ldaF + hc);
                else {
                    float4 g4 = *(const float4*)(Af1 + mrow * ldaF + hc);
                    float4 cc = *(const float4*)(Af2 + mrow * ldaF + hc);
                    v = make_float4(g4.x * cc.x, g4.y * cc.y, g4.z * cc.z, g4.w * cc.w);
                }
                uint32_t off = swz((uint32_t)(rA + s * 16) * 128 + c4 * 8);
                *(uint2*)(smem + buf * 32768 + off) = pack4h(v);
            }
        }

        // ---- stage chunk c+1 ----
        if (c + 1 < NC) {
            const uint32_t o1 = sb + ((c + 1) & 1) * 32768;
            const int k1 = (c + 1) * 64;
            if (AM == 1) {
                #pragma unroll
                for (int s = 0; s < 8; s++)
                    ua[s] = *(const uint2*)(Ug + (size_t)(rA + s * 16) * ldaF + k1 + c4 * 4);
            }
            tileB128(Bp + k1, ldb, o1 + 16384, tid);
            CP_COMMIT();
            CP_WAIT1();
        } else {
            CP_WAIT0();
        }
        __syncthreads();

        const uint32_t o = sb + buf * 32768;
        #pragma unroll
        for (int ks = 0; ks < 4; ks++) {
            const int kb = ks * 32;
            uint32_t rah[4][4], rbh[4][2];
            #pragma unroll
            for (int mi = 0; mi < 4; mi++) {
                uint32_t off = swz((uint32_t)(wM * 64 + mi * 16 + aRow) * 128 + kb + aColB);
                LDSM_X4(rah[mi][0], rah[mi][1], rah[mi][2], rah[mi][3], o + off);
            }
            #pragma unroll
            for (int p = 0; p < 2; p++) {
                uint32_t off = swz((uint32_t)(wN * 32 + p * 16 + bRowP) * 128 + kb + bColB);
                LDSM_X4(rbh[2 * p][0], rbh[2 * p][1], rbh[2 * p + 1][0], rbh[2 * p + 1][1],
                        o + 16384 + off);
            }
            #pragma unroll
            for (int mi = 0; mi < 4; mi++)
                #pragma unroll
                for (int ni = 0; ni < 4; ni++)
                    MMA_F16(acc[mi][ni], rah[mi], rbh[ni]);
        }
        __syncthreads();
    }

    const int rBase = mT + wM * 64 + (lane >> 2);
    const int cBase = nT + wN * 32 + (lane & 3) * 2;
    #pragma unroll
    for (int mi = 0; mi < 4; mi++)
        #pragma unroll
        for (int ni = 0; ni < 4; ni++) {
            const int r0 = rBase + mi * 16;
            const int c0 = cBase + ni * 8;
            float* p = acc[mi][ni];
            if (EM == 0) {
                float* dst = Cf + z * sC;
                *(float2*)(dst + (size_t)r0 * ldc + c0) = make_float2(p[0], p[1]);
                *(float2*)(dst + (size_t)(r0 + 8) * ldc + c0) = make_float2(p[2], p[3]);
            } else {
                float2 bv = *(const float2*)(bias + c0);
                float* dst = Cf + z * sC;
                *(float2*)(dst + (size_t)r0 * ldc + c0) =
                    make_float2(fmaxf(p[0] + bv.x, 0.f), fmaxf(p[1] + bv.y, 0.f));
                *(float2*)(dst + (size_t)(r0 + 8) * ldc + c0) =
                    make_float2(fmaxf(p[2] + bv.x, 0.f), fmaxf(p[3] + bv.y, 0.f));
            }
        }
}

// ======================= prep / softmax kernels ============================
// fused: split(g) + split(WP) + convert(W_out) in one launch
__global__ void prep_all(const float* __restrict__ g, __half* __restrict__ gHi, __half* __restrict__ gLo,
                         const float* __restrict__ WP, __half* __restrict__ WPHi, __half* __restrict__ WPLo,
                         const float* __restrict__ Wo, __half* __restrict__ Wo16)
{
    const int NG = B_ * L_ * H_ / 4;
    const int NW = H_ * H_ / 4;
    const int NO = H_ * 3 * H_ / 4;
    for (int i = blockIdx.x * blockDim.x + threadIdx.x; i < NG + NW + NO;
         i += gridDim.x * blockDim.x) {
        if (i < NG) {
            float4 v = ((const float4*)g)[i];
            uint2 h, l; pack_split4h(v, h, l);
            ((uint2*)gHi)[i] = h; ((uint2*)gLo)[i] = l;
        } else if (i < NG + NW) {
            int j = i - NG;
            float4 v = ((const float4*)WP)[j];
            uint2 h, l; pack_split4h(v, h, l);
            ((uint2*)WPHi)[j] = h; ((uint2*)WPLo)[j] = l;
        } else {
            int j = i - NG - NW;
            ((uint2*)Wo16)[j] = pack4h(((const float4*)Wo)[j]);
        }
    }
}

// gTs[b, h, j] = ID[b,j] * g[b, j, h], single fp16
__global__ void transpose_scale(const float* __restrict__ G, const float* __restrict__ ID,
                                __half* __restrict__ T)
{
    __shared__ float t[32][33];
    const int j0 = blockIdx.x * 32, h0 = blockIdx.y * 32, b = blockIdx.z;
    const float* Gb = G + (size_t)b * L_ * H_;
    #pragma unroll
    for (int r = 0; r < 4; r++) {
        int row = threadIdx.y + r * 8;
        t[row][threadIdx.x] = Gb[(size_t)(j0 + row) * H_ + h0 + threadIdx.x]
                              * ID[b * L_ + j0 + row];
    }
    __syncthreads();
    __half* Tb = T + (size_t)b * H_ * L_;
    #pragma unroll
    for (int r = 0; r < 4; r++) {
        int hr = threadIdx.y + r * 8;
        Tb[(size_t)(h0 + hr) * L_ + j0 + threadIdx.x] = __float2half_rn(t[threadIdx.x][hr]);
    }
}

// combine 32 per-tile partials per column -> ID = 1/D, Fac[t] = exp(pm[t]-M)
__global__ void reduce_stats(const float* __restrict__ Pmax, const float* __restrict__ Psum,
                             float* __restrict__ IDo, float* __restrict__ Fac)
{
    const int idx = blockIdx.x * blockDim.x + threadIdx.x;
    const size_t base = ((size_t)(idx >> 11) * 32) * L_ + (idx & (L_ - 1));
    float M = -1e30f;
    float pm[32];
    #pragma unroll
    for (int t = 0; t < 32; t++) {
        pm[t] = Pmax[base + (size_t)t * L_];
        M = fmaxf(M, pm[t]);
    }
    float D = 0.f;
    #pragma unroll
    for (int t = 0; t < 32; t++) {
        float e = __expf(pm[t] - M);
        D += Psum[base + (size_t)t * L_] * e;
        Fac[base + (size_t)t * L_] = e;
    }
    IDo[idx] = 1.0f / D;
}

// ===========================================================================
extern "C" void kernel_launch(void* const* d_in, const int* in_sizes, int n_in,
                              void* d_out, int out_size)
{
    const float* g     = (const float*)d_in[0];
    const float* WP    = (const float*)d_in[1];
    const float* W_out = (const float*)d_in[2];
    const float* b_out = (const float*)d_in[3];
    float* out = (float*)d_out;

    float *C, *ID, *Pm, *Ps, *Fc;
    __half *U, *gHi, *gLo, *gTs, *WhHi, *WhLo, *WPHi, *WPLo, *Wo16;
    cudaGetSymbolAddress((void**)&U, d_U);
    cudaGetSymbolAddress((void**)&C, d_C);
    cudaGetSymbolAddress((void**)&ID, d_ID);
    cudaGetSymbolAddress((void**)&Pm, d_Pmax);
    cudaGetSymbolAddress((void**)&Ps, d_Psum);
    cudaGetSymbolAddress((void**)&Fc, d_Fac);
    cudaGetSymbolAddress((void**)&gHi, d_gHi);   cudaGetSymbolAddress((void**)&gLo, d_gLo);
    cudaGetSymbolAddress((void**)&gTs, d_gTs);
    cudaGetSymbolAddress((void**)&WhHi, d_WhHi); cudaGetSymbolAddress((void**)&WhLo, d_WhLo);
    cudaGetSymbolAddress((void**)&WPHi, d_WPHi); cudaGetSymbolAddress((void**)&WPLo, d_WPLo);
    cudaGetSymbolAddress((void**)&Wo16, d_Wo16);

    cudaFuncSetAttribute(gemm3p<1>, cudaFuncAttributeMaxDynamicSharedMemorySize, GEMM3_SMEM);
    cudaFuncSetAttribute(gemm3p<3>, cudaFuncAttributeMaxDynamicSharedMemorySize, GEMM3_SMEM);
    cudaFuncSetAttribute(gemm1p<1,0>, cudaFuncAttributeMaxDynamicSharedMemorySize, GEMM1_SMEM);
    cudaFuncSetAttribute(gemm1p<2,2>, cudaFuncAttributeMaxDynamicSharedMemorySize, GEMM1_SMEM);

    // 0) fused splits / converts
    prep_all<<<2048, 256>>>(g, gHi, gLo, WP, WPHi, WPLo, W_out, Wo16);

    // 1) Wh = g @ WP^T  (3-pass, split-fp16 out)
    gemm3p<1><<<dim3(2, 256, 1), 256, GEMM3_SMEM>>>(
        gHi, gLo, WPHi, WPLo, WhHi, WhLo, nullptr, nullptr,
        H_, H_, H_, H_, 0, 0, 0);

    // 2) u[b] = exp(Wh[b] @ g[b]^T - m_tile64) fp16 + col stats (PERSISTENT)
    gemm3p<3><<<PERSIST_GRID, 256, GEMM3_SMEM>>>(
        WhHi, WhLo, gHi, gLo, U, nullptr, Pm, Ps,
        H_, H_, H_, L_, (long)L_ * H_, (long)L_ * H_, (long)L_ * L_);

    // 3) combine partials -> ID, Fac
    reduce_stats<<<(B_ * L_) / 256, 256>>>(Pm, Ps, ID, Fc);

    // 4) gTs = (ID_j * g)^T single fp16
    transpose_scale<<<dim3(L_ / 32, H_ / 32, B_), dim3(32, 8)>>>(g, ID, gTs);

    // 5) c[b] = (u * Fac) @ gTs^T  (1-pass, hmul2 A in-kernel)
    gemm1p<1,0><<<dim3(2, 16, B_), 256, GEMM1_SMEM>>>(
        U, Fc, nullptr, nullptr, gTs, C, nullptr,
        L_, L_, L_, H_, (long)L_ * L_, (long)H_ * L_, (long)L_ * H_);

    // 6) out = relu(cat(g, c, g*c) @ Wo16^T + b)  (1-pass, A built in-kernel)
    gemm1p<2,2><<<dim3(2, 128, 1), 256, GEMM1_SMEM>>>(
        nullptr, nullptr, g, C, Wo16, out, b_out,
        3 * H_, H_, 3 * H_, H_, 0, 0, 0);
}